// round 3
// baseline (speedup 1.0000x reference)
#include <cuda_runtime.h>
#include <cuda_bf16.h>
#include <cuda_fp16.h>

// Problem constants
#define M_ROWS 1024      // B*S = 2*512
#define HDIM   1024
#define HD2    512
#define KEXP   4
#define VDIM   32000
#define N_EXP  128000    // K*V

// ---------------- scratch (device globals; no runtime allocation) ----------------
__device__ __align__(16) __nv_bfloat16 g_xbf[M_ROWS * HDIM];          // RMSNormed x, bf16 (2 MB)
__device__ __align__(16) float         g_gsilu[M_ROWS * HD2];         // silu(x@Wd) (2 MB)
__device__ __align__(16) float         g_gw[M_ROWS * KEXP];           // gate weights (16 KB)
__device__ __align__(16) __half        g_E[(size_t)M_ROWS * N_EXP];   // exp(logits), fp16 (262 MB)

// ---------------- K1: RMSNorm -> bf16 ----------------
__global__ __launch_bounds__(256) void rmsnorm_kernel(const float* __restrict__ hs,
                                                      const float* __restrict__ scale)
{
    const int r = blockIdx.x, tid = threadIdx.x;
    __shared__ float red[256];
    const float4* xp = (const float4*)(hs + (size_t)r * HDIM);
    float4 v = xp[tid];                                  // 256 threads * 4 = 1024
    red[tid] = v.x*v.x + v.y*v.y + v.z*v.z + v.w*v.w;
    __syncthreads();
    #pragma unroll
    for (int s = 128; s > 0; s >>= 1) {
        if (tid < s) red[tid] += red[tid + s];
        __syncthreads();
    }
    float inv = rsqrtf(red[0] * (1.0f / HDIM) + 1e-5f);
    float4 sc = ((const float4*)scale)[tid];
    __nv_bfloat162 p0 = __floats2bfloat162_rn(v.x*inv*sc.x, v.y*inv*sc.y);
    __nv_bfloat162 p1 = __floats2bfloat162_rn(v.z*inv*sc.z, v.w*inv*sc.w);
    uint2 u;
    u.x = *reinterpret_cast<unsigned*>(&p0);
    u.y = *reinterpret_cast<unsigned*>(&p1);
    *reinterpret_cast<uint2*>(&g_xbf[(size_t)r * HDIM + tid * 4]) = u;
}

// ---------------- K2/K4: bf16 mma.sync GEMM, fused epilogue ----------------
// C[M, N] = x_bf16[M, K=1024] @ B[K, N] (B fp32 in gmem, converted to bf16 on the fly)
// MODE 0: out = silu(C + bias) -> g_gsilu (fp32, ld=512)
// MODE 1: out = exp(C)         -> g_E     (fp16, ld=128000)
// CTA tile 128x128, BK=32, 8 warps (2x4), warp tile 64x32, m16n8k16.
template<int MODE>
__global__ __launch_bounds__(256) void gemm_bf16(const float* __restrict__ Bmat,
                                                 const float* __restrict__ bias,
                                                 int ldb)
{
    __shared__ __align__(16) __nv_bfloat16 As[128][40];  // [m][k], pad 40 -> conflict-free
    __shared__ __align__(16) __nv_bfloat16 Bs[128][40];  // [n][k] (transposed)

    const int tid  = threadIdx.x;
    const int lane = tid & 31;
    const int warp = tid >> 5;
    const int wm = warp >> 2;        // 0..1
    const int wn = warp & 3;         // 0..3
    const int m0 = blockIdx.x * 128;
    const int n0 = blockIdx.y * 128;

    float acc[4][4][4];
    #pragma unroll
    for (int i = 0; i < 4; i++)
        #pragma unroll
        for (int j = 0; j < 4; j++)
            #pragma unroll
            for (int q = 0; q < 4; q++) acc[i][j][q] = 0.0f;

    const int l_row  = tid & 127;    // 0..127
    const int k_half = tid >> 7;     // 0..1

    for (int k0 = 0; k0 < HDIM; k0 += 32) {
        // ---- load A tile (bf16, already converted) ----
        {
            const __nv_bfloat16* Ap = g_xbf + (size_t)(m0 + l_row) * HDIM + k0 + k_half * 16;
            uint4 v0 = *(const uint4*)Ap;
            uint4 v1 = *(const uint4*)(Ap + 8);
            *reinterpret_cast<uint4*>(&As[l_row][k_half * 16])     = v0;
            *reinterpret_cast<uint4*>(&As[l_row][k_half * 16 + 8]) = v1;
        }
        // ---- load B tile: fp32 gmem [k][n] -> bf16 smem [n][k] ----
        {
            const float* Bp = Bmat + (size_t)(k0 + k_half * 16) * ldb + n0 + l_row;
            unsigned rr[8];
            #pragma unroll
            for (int j = 0; j < 8; j++) {
                float f0 = Bp[(size_t)(2 * j)     * ldb];
                float f1 = Bp[(size_t)(2 * j + 1) * ldb];
                __nv_bfloat162 p = __floats2bfloat162_rn(f0, f1);
                rr[j] = *reinterpret_cast<unsigned*>(&p);
            }
            uint4 u0 = make_uint4(rr[0], rr[1], rr[2], rr[3]);
            uint4 u1 = make_uint4(rr[4], rr[5], rr[6], rr[7]);
            *reinterpret_cast<uint4*>(&Bs[l_row][k_half * 16])     = u0;
            *reinterpret_cast<uint4*>(&Bs[l_row][k_half * 16 + 8]) = u1;
        }
        __syncthreads();

        #pragma unroll
        for (int ks = 0; ks < 2; ks++) {
            const int kb = ks * 16;
            const int kc = kb + (lane & 3) * 2;
            unsigned a[4][4], b[4][2];
            #pragma unroll
            for (int mt = 0; mt < 4; mt++) {
                int r0 = wm * 64 + mt * 16 + (lane >> 2);
                a[mt][0] = *reinterpret_cast<const unsigned*>(&As[r0    ][kc    ]);
                a[mt][1] = *reinterpret_cast<const unsigned*>(&As[r0 + 8][kc    ]);
                a[mt][2] = *reinterpret_cast<const unsigned*>(&As[r0    ][kc + 8]);
                a[mt][3] = *reinterpret_cast<const unsigned*>(&As[r0 + 8][kc + 8]);
            }
            #pragma unroll
            for (int nt = 0; nt < 4; nt++) {
                int c0 = wn * 32 + nt * 8 + (lane >> 2);
                b[nt][0] = *reinterpret_cast<const unsigned*>(&Bs[c0][kc    ]);
                b[nt][1] = *reinterpret_cast<const unsigned*>(&Bs[c0][kc + 8]);
            }
            #pragma unroll
            for (int mt = 0; mt < 4; mt++)
                #pragma unroll
                for (int nt = 0; nt < 4; nt++) {
                    asm volatile(
                        "mma.sync.aligned.m16n8k16.row.col.f32.bf16.bf16.f32 "
                        "{%0,%1,%2,%3}, {%4,%5,%6,%7}, {%8,%9}, {%0,%1,%2,%3};\n"
                        : "+f"(acc[mt][nt][0]), "+f"(acc[mt][nt][1]),
                          "+f"(acc[mt][nt][2]), "+f"(acc[mt][nt][3])
                        : "r"(a[mt][0]), "r"(a[mt][1]), "r"(a[mt][2]), "r"(a[mt][3]),
                          "r"(b[nt][0]), "r"(b[nt][1]));
                }
        }
        __syncthreads();
    }

    // ---- epilogue ----
    #pragma unroll
    for (int mt = 0; mt < 4; mt++) {
        int r0 = m0 + wm * 64 + mt * 16 + (lane >> 2);
        #pragma unroll
        for (int nt = 0; nt < 4; nt++) {
            int nc = n0 + wn * 32 + nt * 8 + (lane & 3) * 2;
            if (MODE == 1) {
                __half2 h0 = __floats2half2_rn(__expf(acc[mt][nt][0]), __expf(acc[mt][nt][1]));
                __half2 h1 = __floats2half2_rn(__expf(acc[mt][nt][2]), __expf(acc[mt][nt][3]));
                *reinterpret_cast<__half2*>(&g_E[(size_t)r0 * N_EXP + nc])       = h0;
                *reinterpret_cast<__half2*>(&g_E[(size_t)(r0 + 8) * N_EXP + nc]) = h1;
            } else {
                float b0 = bias[nc], b1 = bias[nc + 1];
                float v;
                v = acc[mt][nt][0] + b0; g_gsilu[r0 * HD2 + nc]           = v / (1.0f + __expf(-v));
                v = acc[mt][nt][1] + b1; g_gsilu[r0 * HD2 + nc + 1]       = v / (1.0f + __expf(-v));
                v = acc[mt][nt][2] + b0; g_gsilu[(r0 + 8) * HD2 + nc]     = v / (1.0f + __expf(-v));
                v = acc[mt][nt][3] + b1; g_gsilu[(r0 + 8) * HD2 + nc + 1] = v / (1.0f + __expf(-v));
            }
        }
    }
}

// ---------------- K3: gate-up GEMV (K=4 outputs) + softmax over experts ----------------
__global__ __launch_bounds__(128) void gate_softmax_kernel(const float* __restrict__ Wu,
                                                           const float* __restrict__ bu)
{
    const int r = blockIdx.x, tid = threadIdx.x;
    float p0 = 0.f, p1 = 0.f, p2 = 0.f, p3 = 0.f;
    const float* gr = g_gsilu + (size_t)r * HD2;
    for (int d = tid; d < HD2; d += 128) {
        float gv = gr[d];
        float4 w = ((const float4*)Wu)[d];               // Wu[d][0..3]
        p0 += gv * w.x; p1 += gv * w.y; p2 += gv * w.z; p3 += gv * w.w;
    }
    __shared__ float red[4][128];
    red[0][tid] = p0; red[1][tid] = p1; red[2][tid] = p2; red[3][tid] = p3;
    __syncthreads();
    #pragma unroll
    for (int s = 64; s > 0; s >>= 1) {
        if (tid < s) {
            red[0][tid] += red[0][tid + s];
            red[1][tid] += red[1][tid + s];
            red[2][tid] += red[2][tid + s];
            red[3][tid] += red[3][tid + s];
        }
        __syncthreads();
    }
    if (tid == 0) {
        float l[4];
        #pragma unroll
        for (int k = 0; k < 4; k++) l[k] = red[k][0] + bu[k];
        float m = fmaxf(fmaxf(l[0], l[1]), fmaxf(l[2], l[3]));
        float e[4]; float s = 0.f;
        #pragma unroll
        for (int k = 0; k < 4; k++) { e[k] = __expf(l[k] - m); s += e[k]; }
        float inv = 1.0f / s;
        #pragma unroll
        for (int k = 0; k < 4; k++) g_gw[r * 4 + k] = e[k] * inv;
    }
}

// ---------------- K5: per-row softmax denominators + mixture + log ----------------
__global__ __launch_bounds__(256) void mix_out_kernel(float* __restrict__ out)
{
    const int r = blockIdx.x, tid = threadIdx.x;
    __shared__ float red[256];
    __shared__ float coef[4];
    const __half2* Er = reinterpret_cast<const __half2*>(g_E + (size_t)r * N_EXP);
    const int HV = VDIM / 2;                             // 16000 half2 per (row, k)

    float sums[4];
    #pragma unroll
    for (int k = 0; k < 4; k++) {
        float p = 0.f;
        const __half2* Ek = Er + k * HV;
        for (int v = tid; v < HV; v += 256) {
            float2 f = __half22float2(Ek[v]);
            p += f.x + f.y;
        }
        red[tid] = p; __syncthreads();
        #pragma unroll
        for (int s = 128; s > 0; s >>= 1) {
            if (tid < s) red[tid] += red[tid + s];
            __syncthreads();
        }
        sums[k] = red[0];
        __syncthreads();
    }
    if (tid < 4) coef[tid] = g_gw[r * 4 + tid] / sums[tid];
    __syncthreads();
    const float c0 = coef[0], c1 = coef[1], c2 = coef[2], c3 = coef[3];

    float2* outr = reinterpret_cast<float2*>(out + (size_t)r * VDIM);
    for (int v = tid; v < HV; v += 256) {
        float2 f0 = __half22float2(Er[v]);
        float2 f1 = __half22float2(Er[HV + v]);
        float2 f2 = __half22float2(Er[2 * HV + v]);
        float2 f3 = __half22float2(Er[3 * HV + v]);
        float mx = c0 * f0.x + c1 * f1.x + c2 * f2.x + c3 * f3.x;
        float my = c0 * f0.y + c1 * f1.y + c2 * f2.y + c3 * f3.y;
        outr[v] = make_float2(logf(mx + 1e-10f), logf(my + 1e-10f));
    }
}

// ---------------- launch ----------------
extern "C" void kernel_launch(void* const* d_in, const int* in_sizes, int n_in,
                              void* d_out, int out_size)
{
    const float* hs  = (const float*)d_in[0];   // hidden_states (2,512,1024)
    const float* rs  = (const float*)d_in[1];   // rms_scale (1024)
    const float* gdw = (const float*)d_in[2];   // gate_down_w (1024,512)
    const float* gdb = (const float*)d_in[3];   // gate_down_b (512)
    const float* guw = (const float*)d_in[4];   // gate_up_w (512,4)
    const float* gub = (const float*)d_in[5];   // gate_up_b (4)
    const float* ew  = (const float*)d_in[6];   // expert_w (1024,128000)
    float* out = (float*)d_out;                 // (2,512,32000) fp32

    rmsnorm_kernel<<<M_ROWS, 256>>>(hs, rs);
    gemm_bf16<0><<<dim3(8, 4), 256>>>(gdw, gdb, HD2);       // gate down + silu
    gate_softmax_kernel<<<M_ROWS, 128>>>(guw, gub);         // gate up + softmax(K)
    gemm_bf16<1><<<dim3(8, 1000), 256>>>(ew, nullptr, N_EXP); // expert GEMM + exp
    mix_out_kernel<<<M_ROWS, 256>>>(out);                   // sums + mix + log
}

// round 6
// speedup vs baseline: 1.7842x; 1.7842x over previous
#include <cuda_runtime.h>
#include <cuda_bf16.h>
#include <cuda_fp16.h>
#include <cstdint>

// Problem constants
#define M_ROWS 1024      // B*S
#define HDIM   1024
#define HD2    512
#define VDIM   32000
#define N_EXP  128000    // K*V
#define NBLK   1000      // n-blocks of 128 in expert GEMM (250 per expert)

// ---------------- scratch (device globals; no runtime allocation) ----------------
__device__ __align__(16) __nv_bfloat16 g_xbf[M_ROWS * HDIM];            // RMSNormed x (2 MB)
__device__ __align__(16) __nv_bfloat16 g_wt[(size_t)N_EXP * HDIM];      // expert_w^T bf16 (262 MB)
__device__ __align__(16) float         g_gsilu[M_ROWS * HD2];
__device__ __align__(16) float         g_gw[M_ROWS * 4];
__device__ __align__(16) __half        g_E[(size_t)M_ROWS * N_EXP];     // exp(logits) (262 MB)
__device__ __align__(16) float         g_psum[(size_t)M_ROWS * NBLK];   // per-block row sums (4 MB)

// ---------------- helpers ----------------
__device__ __forceinline__ uint32_t cvta_s(const void* p) {
    return (uint32_t)__cvta_generic_to_shared(p);
}
// SW128 swizzle on byte offsets (1KB atom, 128B rows)
__device__ __forceinline__ uint32_t swz128(uint32_t o) { return o ^ ((o >> 3) & 0x70); }

__device__ __forceinline__ void ldsm_x4(uint32_t& r0, uint32_t& r1, uint32_t& r2, uint32_t& r3,
                                        uint32_t addr) {
    asm volatile("ldmatrix.sync.aligned.m8n8.x4.shared.b16 {%0,%1,%2,%3}, [%4];"
                 : "=r"(r0), "=r"(r1), "=r"(r2), "=r"(r3) : "r"(addr));
}

// ---------------- K0: transpose + convert expert_w fp32[K][N] -> bf16[N][K] ----------------
__global__ __launch_bounds__(256) void transpose_convert(const float* __restrict__ W)
{
    __shared__ float t[64][33];
    const int n0 = blockIdx.x * 32;
    const int k0 = blockIdx.y * 64;
    const int c  = threadIdx.x & 31;
    const int r0 = threadIdx.x >> 5;
    #pragma unroll
    for (int i = 0; i < 8; i++) {
        int k = r0 + i * 8;
        t[k][c] = W[(size_t)(k0 + k) * N_EXP + n0 + c];
    }
    __syncthreads();
    const int kk = (threadIdx.x & 31) * 2;
    #pragma unroll
    for (int i = 0; i < 4; i++) {
        int nl = (threadIdx.x >> 5) + i * 8;
        __nv_bfloat162 p = __floats2bfloat162_rn(t[kk][nl], t[kk + 1][nl]);
        *reinterpret_cast<__nv_bfloat162*>(&g_wt[(size_t)(n0 + nl) * HDIM + k0 + kk]) = p;
    }
}

// ---------------- K1: RMSNorm -> bf16 ----------------
__global__ __launch_bounds__(256) void rmsnorm_kernel(const float* __restrict__ hs,
                                                      const float* __restrict__ scale)
{
    const int r = blockIdx.x, tid = threadIdx.x;
    __shared__ float red[256];
    const float4* xp = (const float4*)(hs + (size_t)r * HDIM);
    float4 v = xp[tid];
    red[tid] = v.x*v.x + v.y*v.y + v.z*v.z + v.w*v.w;
    __syncthreads();
    #pragma unroll
    for (int s = 128; s > 0; s >>= 1) {
        if (tid < s) red[tid] += red[tid + s];
        __syncthreads();
    }
    float inv = rsqrtf(red[0] * (1.0f / HDIM) + 1e-5f);
    float4 sc = ((const float4*)scale)[tid];
    __nv_bfloat162 p0 = __floats2bfloat162_rn(v.x*inv*sc.x, v.y*inv*sc.y);
    __nv_bfloat162 p1 = __floats2bfloat162_rn(v.z*inv*sc.z, v.w*inv*sc.w);
    uint2 u;
    u.x = *reinterpret_cast<unsigned*>(&p0);
    u.y = *reinterpret_cast<unsigned*>(&p1);
    *reinterpret_cast<uint2*>(&g_xbf[(size_t)r * HDIM + tid * 4]) = u;
}

// ---------------- K2: gate-down GEMM (small; unchanged from passing R3) ----------------
__global__ __launch_bounds__(256) void gemm_gate(const float* __restrict__ Bmat,
                                                 const float* __restrict__ bias)
{
    __shared__ __align__(16) __nv_bfloat16 As[128][40];
    __shared__ __align__(16) __nv_bfloat16 Bs[128][40];

    const int tid  = threadIdx.x;
    const int lane = tid & 31;
    const int warp = tid >> 5;
    const int wm = warp >> 2, wn = warp & 3;
    const int m0 = blockIdx.x * 128;
    const int n0 = blockIdx.y * 128;
    const int ldb = HD2;

    float acc[4][4][4];
    #pragma unroll
    for (int i = 0; i < 4; i++)
        #pragma unroll
        for (int j = 0; j < 4; j++)
            #pragma unroll
            for (int q = 0; q < 4; q++) acc[i][j][q] = 0.0f;

    const int l_row = tid & 127, k_half = tid >> 7;

    for (int k0 = 0; k0 < HDIM; k0 += 32) {
        {
            const __nv_bfloat16* Ap = g_xbf + (size_t)(m0 + l_row) * HDIM + k0 + k_half * 16;
            *reinterpret_cast<uint4*>(&As[l_row][k_half * 16])     = *(const uint4*)Ap;
            *reinterpret_cast<uint4*>(&As[l_row][k_half * 16 + 8]) = *(const uint4*)(Ap + 8);
        }
        {
            const float* Bp = Bmat + (size_t)(k0 + k_half * 16) * ldb + n0 + l_row;
            unsigned rr[8];
            #pragma unroll
            for (int j = 0; j < 8; j++) {
                __nv_bfloat162 p = __floats2bfloat162_rn(Bp[(size_t)(2*j)*ldb], Bp[(size_t)(2*j+1)*ldb]);
                rr[j] = *reinterpret_cast<unsigned*>(&p);
            }
            *reinterpret_cast<uint4*>(&Bs[l_row][k_half * 16])     = make_uint4(rr[0],rr[1],rr[2],rr[3]);
            *reinterpret_cast<uint4*>(&Bs[l_row][k_half * 16 + 8]) = make_uint4(rr[4],rr[5],rr[6],rr[7]);
        }
        __syncthreads();
        #pragma unroll
        for (int ks = 0; ks < 2; ks++) {
            const int kc = ks * 16 + (lane & 3) * 2;
            unsigned a[4][4], b[4][2];
            #pragma unroll
            for (int mt = 0; mt < 4; mt++) {
                int r0 = wm * 64 + mt * 16 + (lane >> 2);
                a[mt][0] = *reinterpret_cast<const unsigned*>(&As[r0    ][kc    ]);
                a[mt][1] = *reinterpret_cast<const unsigned*>(&As[r0 + 8][kc    ]);
                a[mt][2] = *reinterpret_cast<const unsigned*>(&As[r0    ][kc + 8]);
                a[mt][3] = *reinterpret_cast<const unsigned*>(&As[r0 + 8][kc + 8]);
            }
            #pragma unroll
            for (int nt = 0; nt < 4; nt++) {
                int c0 = wn * 32 + nt * 8 + (lane >> 2);
                b[nt][0] = *reinterpret_cast<const unsigned*>(&Bs[c0][kc    ]);
                b[nt][1] = *reinterpret_cast<const unsigned*>(&Bs[c0][kc + 8]);
            }
            #pragma unroll
            for (int mt = 0; mt < 4; mt++)
                #pragma unroll
                for (int nt = 0; nt < 4; nt++) {
                    asm volatile(
                        "mma.sync.aligned.m16n8k16.row.col.f32.bf16.bf16.f32 "
                        "{%0,%1,%2,%3}, {%4,%5,%6,%7}, {%8,%9}, {%0,%1,%2,%3};\n"
                        : "+f"(acc[mt][nt][0]), "+f"(acc[mt][nt][1]),
                          "+f"(acc[mt][nt][2]), "+f"(acc[mt][nt][3])
                        : "r"(a[mt][0]), "r"(a[mt][1]), "r"(a[mt][2]), "r"(a[mt][3]),
                          "r"(b[nt][0]), "r"(b[nt][1]));
                }
        }
        __syncthreads();
    }
    #pragma unroll
    for (int mt = 0; mt < 4; mt++) {
        int r0 = m0 + wm * 64 + mt * 16 + (lane >> 2);
        #pragma unroll
        for (int nt = 0; nt < 4; nt++) {
            int nc = n0 + wn * 32 + nt * 8 + (lane & 3) * 2;
            float b0 = bias[nc], b1 = bias[nc + 1];
            float v;
            v = acc[mt][nt][0] + b0; g_gsilu[r0 * HD2 + nc]           = v / (1.0f + __expf(-v));
            v = acc[mt][nt][1] + b1; g_gsilu[r0 * HD2 + nc + 1]       = v / (1.0f + __expf(-v));
            v = acc[mt][nt][2] + b0; g_gsilu[(r0 + 8) * HD2 + nc]     = v / (1.0f + __expf(-v));
            v = acc[mt][nt][3] + b1; g_gsilu[(r0 + 8) * HD2 + nc + 1] = v / (1.0f + __expf(-v));
        }
    }
}

// ---------------- K3: gate-up GEMV + softmax over 4 experts ----------------
__global__ __launch_bounds__(128) void gate_softmax_kernel(const float* __restrict__ Wu,
                                                           const float* __restrict__ bu)
{
    const int r = blockIdx.x, tid = threadIdx.x;
    float p0 = 0.f, p1 = 0.f, p2 = 0.f, p3 = 0.f;
    const float* gr = g_gsilu + (size_t)r * HD2;
    for (int d = tid; d < HD2; d += 128) {
        float gv = gr[d];
        float4 w = ((const float4*)Wu)[d];
        p0 += gv * w.x; p1 += gv * w.y; p2 += gv * w.z; p3 += gv * w.w;
    }
    __shared__ float red[4][128];
    red[0][tid] = p0; red[1][tid] = p1; red[2][tid] = p2; red[3][tid] = p3;
    __syncthreads();
    #pragma unroll
    for (int s = 64; s > 0; s >>= 1) {
        if (tid < s) {
            red[0][tid] += red[0][tid + s]; red[1][tid] += red[1][tid + s];
            red[2][tid] += red[2][tid + s]; red[3][tid] += red[3][tid + s];
        }
        __syncthreads();
    }
    if (tid == 0) {
        float l[4];
        #pragma unroll
        for (int k = 0; k < 4; k++) l[k] = red[k][0] + bu[k];
        float m = fmaxf(fmaxf(l[0], l[1]), fmaxf(l[2], l[3]));
        float e[4]; float s = 0.f;
        #pragma unroll
        for (int k = 0; k < 4; k++) { e[k] = __expf(l[k] - m); s += e[k]; }
        float inv = 1.0f / s;
        #pragma unroll
        for (int k = 0; k < 4; k++) g_gw[r * 4 + k] = e[k] * inv;
    }
}

// ---------------- K4: expert GEMM (mma.sync + ldmatrix + cp.async 3-stage) ----------------
// CTA tile 128x128, BK=64, 16 k-tiles, 8 warps (2x4), warp tile 64x32.
// smem: 3 stages x (A 16KB + B 16KB) = 98304, + s_rows 4x128 floats = 2048 -> 100352.
#define STAGE_BYTES 32768
#define B_OFF       16384
#define SMEM_GEMM   100352

extern __shared__ char dsm[];

__global__ void __launch_bounds__(256, 2) expert_gemm()
{
    const int tid  = threadIdx.x;
    const int lane = tid & 31;
    const int warp = tid >> 5;
    const int wm = warp >> 2, wn = warp & 3;
    const int m0 = blockIdx.x * 128;
    const int n0 = blockIdx.y * 128;
    const uint32_t sbase = cvta_s(dsm);

    float acc[4][4][4];
    #pragma unroll
    for (int i = 0; i < 4; i++)
        #pragma unroll
        for (int j = 0; j < 4; j++)
            #pragma unroll
            for (int q = 0; q < 4; q++) acc[i][j][q] = 0.0f;

    // ---- cp.async stage loader: 256 threads, 16B each, 4 rows A + 4 rows B ----
    const int lrow = tid >> 3;            // 0..31
    const int seg  = tid & 7;             // 0..7
    const __nv_bfloat16* Abase_g = g_xbf + (size_t)(m0 + lrow) * HDIM + seg * 8;
    const __nv_bfloat16* Bbase_g = g_wt  + (size_t)(n0 + lrow) * HDIM + seg * 8;

    auto load_stage = [&](int kt, int buf) {
        const uint32_t sA = sbase + buf * STAGE_BYTES;
        const uint32_t sB = sA + B_OFF;
        const int koff = kt * 64;
        #pragma unroll
        for (int i = 0; i < 4; i++) {
            uint32_t d = sA + swz128((lrow + i * 32) * 128 + seg * 16);
            asm volatile("cp.async.cg.shared.global [%0], [%1], 16;"
                         :: "r"(d), "l"(Abase_g + koff + (size_t)i * 32 * HDIM) : "memory");
        }
        #pragma unroll
        for (int i = 0; i < 4; i++) {
            uint32_t d = sB + swz128((lrow + i * 32) * 128 + seg * 16);
            asm volatile("cp.async.cg.shared.global [%0], [%1], 16;"
                         :: "r"(d), "l"(Bbase_g + koff + (size_t)i * 32 * HDIM) : "memory");
        }
        asm volatile("cp.async.commit_group;" ::: "memory");
    };

    load_stage(0, 0);
    load_stage(1, 1);

    // per-lane ldmatrix address components
    const int a_row_in16 = lane & 15;          // row within m16 tile
    const int a_khalf    = (lane >> 4) * 16;   // 0 or 16 bytes
    const int b_nrow     = (lane & 7) + ((lane >> 4) & 1) * 8;  // row within n16 pair
    const int b_khalf    = ((lane >> 3) & 1) * 16;

    for (int kt = 0; kt < 16; kt++) {
        const int buf = kt % 3;
        if (kt < 15) asm volatile("cp.async.wait_group 1;" ::: "memory");
        else         asm volatile("cp.async.wait_group 0;" ::: "memory");
        __syncthreads();
        // prefetch kt+2 into buffer (kt+2)%3 == (kt-1)%3 (freed by the barrier above)
        if (kt + 2 < 16) load_stage(kt + 2, (kt + 2) % 3);

        const uint32_t sA = sbase + buf * STAGE_BYTES;
        const uint32_t sB = sA + B_OFF;

        #pragma unroll
        for (int ks = 0; ks < 4; ks++) {
            const int kb = ks * 32;            // byte offset of this k16 step
            unsigned a[4][4], b[4][2];
            #pragma unroll
            for (int mt = 0; mt < 4; mt++) {
                int row = wm * 64 + mt * 16 + a_row_in16;
                uint32_t addr = sA + row * 128 + ((kb + a_khalf) ^ ((row & 7) * 16));
                ldsm_x4(a[mt][0], a[mt][1], a[mt][2], a[mt][3], addr);
            }
            #pragma unroll
            for (int np = 0; np < 2; np++) {   // pairs of n8 tiles
                int row = wn * 32 + np * 16 + b_nrow;
                uint32_t addr = sB + row * 128 + ((kb + b_khalf) ^ ((row & 7) * 16));
                ldsm_x4(b[np*2][0], b[np*2][1], b[np*2+1][0], b[np*2+1][1], addr);
            }
            #pragma unroll
            for (int mt = 0; mt < 4; mt++)
                #pragma unroll
                for (int nt = 0; nt < 4; nt++) {
                    asm volatile(
                        "mma.sync.aligned.m16n8k16.row.col.f32.bf16.bf16.f32 "
                        "{%0,%1,%2,%3}, {%4,%5,%6,%7}, {%8,%9}, {%0,%1,%2,%3};\n"
                        : "+f"(acc[mt][nt][0]), "+f"(acc[mt][nt][1]),
                          "+f"(acc[mt][nt][2]), "+f"(acc[mt][nt][3])
                        : "r"(a[mt][0]), "r"(a[mt][1]), "r"(a[mt][2]), "r"(a[mt][3]),
                          "r"(b[nt][0]), "r"(b[nt][1]));
                }
        }
        __syncthreads();   // buffer 'buf' free for reuse two iterations later
    }

    // ---- epilogue: exp -> fp16 store + deterministic row sums ----
    float* s_rows = reinterpret_cast<float*>(dsm + 3 * STAGE_BYTES);   // [4][128]
    float rs[4][2];
    #pragma unroll
    for (int mt = 0; mt < 4; mt++) { rs[mt][0] = 0.f; rs[mt][1] = 0.f; }

    #pragma unroll
    for (int mt = 0; mt < 4; mt++) {
        int rg = m0 + wm * 64 + mt * 16 + (lane >> 2);
        #pragma unroll
        for (int nt = 0; nt < 4; nt++) {
            int nc = n0 + wn * 32 + nt * 8 + (lane & 3) * 2;
            float e0 = __expf(acc[mt][nt][0]);
            float e1 = __expf(acc[mt][nt][1]);
            float e2 = __expf(acc[mt][nt][2]);
            float e3 = __expf(acc[mt][nt][3]);
            rs[mt][0] += e0 + e1;
            rs[mt][1] += e2 + e3;
            __half2 h0 = __floats2half2_rn(e0, e1);
            __half2 h1 = __floats2half2_rn(e2, e3);
            *reinterpret_cast<__half2*>(&g_E[(size_t)rg * N_EXP + nc])       = h0;
            *reinterpret_cast<__half2*>(&g_E[(size_t)(rg + 8) * N_EXP + nc]) = h1;
        }
    }
    // quad-reduce (lanes sharing the same rows) then stage per-warp partials
    #pragma unroll
    for (int mt = 0; mt < 4; mt++) {
        #pragma unroll
        for (int h = 0; h < 2; h++) {
            float v = rs[mt][h];
            v += __shfl_xor_sync(0xffffffff, v, 1);
            v += __shfl_xor_sync(0xffffffff, v, 2);
            if ((lane & 3) == 0)
                s_rows[wn * 128 + wm * 64 + mt * 16 + (lane >> 2) + h * 8] = v;
        }
    }
    __syncthreads();
    if (tid < 128) {
        float t = s_rows[tid] + s_rows[128 + tid] + s_rows[256 + tid] + s_rows[384 + tid];
        g_psum[(size_t)(m0 + tid) * NBLK + blockIdx.y] = t;
    }
}

// ---------------- K5: coefs from psums + mixture + log (single E pass) ----------------
__global__ __launch_bounds__(256) void mix_out_kernel(float* __restrict__ out)
{
    const int r = blockIdx.x, tid = threadIdx.x;
    __shared__ float s_coef[4];
    if (tid < 128) {
        int e = tid >> 5, lane = tid & 31;
        float a = 0.f;
        for (int j = lane; j < 250; j += 32)
            a += g_psum[(size_t)r * NBLK + e * 250 + j];
        #pragma unroll
        for (int s = 16; s; s >>= 1) a += __shfl_xor_sync(0xffffffff, a, s);
        if (lane == 0) s_coef[e] = g_gw[r * 4 + e] / a;
    }
    __syncthreads();
    const float c0 = s_coef[0], c1 = s_coef[1], c2 = s_coef[2], c3 = s_coef[3];
    const __half2* Er = reinterpret_cast<const __half2*>(g_E + (size_t)r * N_EXP);
    float2* outr = reinterpret_cast<float2*>(out + (size_t)r * VDIM);
    const int HV = VDIM / 2;
    for (int v = tid; v < HV; v += 256) {
        float2 f0 = __half22float2(Er[v]);
        float2 f1 = __half22float2(Er[HV + v]);
        float2 f2 = __half22float2(Er[2 * HV + v]);
        float2 f3 = __half22float2(Er[3 * HV + v]);
        float mx = c0 * f0.x + c1 * f1.x + c2 * f2.x + c3 * f3.x;
        float my = c0 * f0.y + c1 * f1.y + c2 * f2.y + c3 * f3.y;
        outr[v] = make_float2(__logf(mx + 1e-10f), __logf(my + 1e-10f));
    }
}

// ---------------- launch ----------------
extern "C" void kernel_launch(void* const* d_in, const int* in_sizes, int n_in,
                              void* d_out, int out_size)
{
    const float* hs  = (const float*)d_in[0];
    const float* rs  = (const float*)d_in[1];
    const float* gdw = (const float*)d_in[2];
    const float* gdb = (const float*)d_in[3];
    const float* guw = (const float*)d_in[4];
    const float* gub = (const float*)d_in[5];
    const float* ew  = (const float*)d_in[6];
    float* out = (float*)d_out;

    cudaFuncSetAttribute(expert_gemm, cudaFuncAttributeMaxDynamicSharedMemorySize, SMEM_GEMM);

    rmsnorm_kernel<<<M_ROWS, 256>>>(hs, rs);
    transpose_convert<<<dim3(N_EXP / 32, HDIM / 64), 256>>>(ew);
    gemm_gate<<<dim3(8, 4), 256>>>(gdw, gdb);
    gate_softmax_kernel<<<M_ROWS, 128>>>(guw, gub);
    expert_gemm<<<dim3(8, NBLK), 256, SMEM_GEMM>>>();
    mix_out_kernel<<<M_ROWS, 256>>>(out);
}